// round 4
// baseline (speedup 1.0000x reference)
#include <cuda_runtime.h>
#include <cuda_bf16.h>
#include <cstdint>

#define Bn 256
#define Sn 365
#define INn 5
#define SCAn 27
#define Hn 256
#define Mn (Bn*Sn)          // 93440, m = t*256 + b

// scratch (device globals; no runtime allocation)
__device__ float g_a[(size_t)Mn * Hn];        // sigmoid(sca@w_a^T + b_a)
__device__ float g_pre[(size_t)Mn * 4 * Hn];  // [m][gate i,f,o,g][256]

__device__ __forceinline__ float sigf(float x) { return 1.0f / (1.0f + __expf(-x)); }

// ========================== Kernel A ==========================
__global__ __launch_bounds__(256) void kernelA(const float* __restrict__ xsca,
                                               const float* __restrict__ w_a,
                                               const float* __restrict__ b_a) {
    __shared__ float wsh[Hn * SCAn];
    __shared__ float ssh[64][28];
    int tid = threadIdx.x;
    int m0 = blockIdx.x * 64;
    for (int i = tid; i < Hn * SCAn; i += 256) wsh[i] = w_a[i];
    for (int i = tid; i < 64 * SCAn; i += 256) {
        int r = i / SCAn, k = i - r * SCAn;
        int m = m0 + r, t = m >> 8, b = m & 255;
        ssh[r][k] = xsca[((size_t)b * Sn + t) * SCAn + k];
    }
    __syncthreads();
    float wr[SCAn];
#pragma unroll
    for (int k = 0; k < SCAn; k++) wr[k] = wsh[tid * SCAn + k];
    float bias = b_a[tid];
    for (int r = 0; r < 64; r++) {
        float s = bias;
#pragma unroll
        for (int k = 0; k < SCAn; k++) s = fmaf(ssh[r][k], wr[k], s);
        g_a[(size_t)(m0 + r) * Hn + tid] = sigf(s);
    }
}

// ========================== Kernel B ==========================
// g_pre[m][gate*256+j] = bias + x(5)·w_gx + (gate<3 ? a(256)·w_ga : 0)
// grid (8 colTiles, 730 rowTiles) x 256 threads; 128x128 tile, 8x8 micro, BK=16
__global__ __launch_bounds__(256) void kernelB(
    const float* __restrict__ xin,
    const float* __restrict__ w_ix, const float* __restrict__ w_ia, const float* __restrict__ b_i,
    const float* __restrict__ w_fx, const float* __restrict__ w_fa, const float* __restrict__ b_f,
    const float* __restrict__ w_ox, const float* __restrict__ w_oa, const float* __restrict__ b_o,
    const float* __restrict__ w_gx, const float* __restrict__ b_g)
{
    __shared__ float Ash[16][136];
    __shared__ float Bsh[16][136];
    __shared__ float Xs[128][6];
    __shared__ float Wxs[128][6];
    __shared__ float Bias[128];

    int ct = blockIdx.x, rt = blockIdx.y;
    int gate = ct >> 1, jg0 = (ct & 1) * 128;
    int tid = threadIdx.x, tx = tid & 15, ty = tid >> 4;
    int m0 = rt * 128;

    const float* wxp = (gate == 0) ? w_ix : (gate == 1) ? w_fx : (gate == 2) ? w_ox : w_gx;
    const float* wap = (gate == 0) ? w_ia : (gate == 1) ? w_fa : w_oa;
    const float* bp  = (gate == 0) ? b_i  : (gate == 1) ? b_f  : (gate == 2) ? b_o : b_g;

    for (int i = tid; i < 128 * INn; i += 256) {
        int r = i / INn, k = i - r * INn;
        int m = m0 + r, t = m >> 8, b = m & 255;
        Xs[r][k] = xin[((size_t)b * Sn + t) * INn + k];
    }
    for (int i = tid; i < 128 * INn; i += 256) {
        int c = i / INn, k = i - c * INn;
        Wxs[c][k] = wxp[(jg0 + c) * INn + k];
    }
    if (tid < 128) Bias[tid] = bp[jg0 + tid];

    float acc[8][8];
#pragma unroll
    for (int i = 0; i < 8; i++)
#pragma unroll
        for (int j = 0; j < 8; j++) acc[i][j] = 0.0f;

    if (gate < 3) {
        int r = tid >> 1, kq = (tid & 1) * 8;
        for (int kt = 0; kt < 16; kt++) {
            __syncthreads();
            const float* sa = &g_a[(size_t)(m0 + r) * Hn + kt * 16 + kq];
            float4 a0 = *(const float4*)sa, a1 = *(const float4*)(sa + 4);
            Ash[kq + 0][r] = a0.x; Ash[kq + 1][r] = a0.y; Ash[kq + 2][r] = a0.z; Ash[kq + 3][r] = a0.w;
            Ash[kq + 4][r] = a1.x; Ash[kq + 5][r] = a1.y; Ash[kq + 6][r] = a1.z; Ash[kq + 7][r] = a1.w;
            const float* sb = &wap[(size_t)(jg0 + r) * Hn + kt * 16 + kq];
            float4 b0 = *(const float4*)sb, b1 = *(const float4*)(sb + 4);
            Bsh[kq + 0][r] = b0.x; Bsh[kq + 1][r] = b0.y; Bsh[kq + 2][r] = b0.z; Bsh[kq + 3][r] = b0.w;
            Bsh[kq + 4][r] = b1.x; Bsh[kq + 5][r] = b1.y; Bsh[kq + 6][r] = b1.z; Bsh[kq + 7][r] = b1.w;
            __syncthreads();
#pragma unroll
            for (int kk = 0; kk < 16; kk++) {
                float4 x0 = *(const float4*)&Ash[kk][ty * 4];
                float4 x1 = *(const float4*)&Ash[kk][ty * 4 + 64];
                float4 y0 = *(const float4*)&Bsh[kk][tx * 4];
                float4 y1 = *(const float4*)&Bsh[kk][tx * 4 + 64];
                float av[8] = {x0.x, x0.y, x0.z, x0.w, x1.x, x1.y, x1.z, x1.w};
                float bv[8] = {y0.x, y0.y, y0.z, y0.w, y1.x, y1.y, y1.z, y1.w};
#pragma unroll
                for (int i = 0; i < 8; i++)
#pragma unroll
                    for (int j = 0; j < 8; j++) acc[i][j] = fmaf(av[i], bv[j], acc[i][j]);
            }
        }
    }
    __syncthreads();

#pragma unroll
    for (int i = 0; i < 8; i++) {
        int rr = ty * 4 + (i & 3) + ((i >> 2) * 64);
        float xr[INn];
#pragma unroll
        for (int k = 0; k < INn; k++) xr[k] = Xs[rr][k];
        float val[8];
#pragma unroll
        for (int j = 0; j < 8; j++) {
            int cc = tx * 4 + (j & 3) + ((j >> 2) * 64);
            float s = acc[i][j] + Bias[cc];
#pragma unroll
            for (int k = 0; k < INn; k++) s = fmaf(xr[k], Wxs[cc][k], s);
            val[j] = s;
        }
        size_t base = (size_t)(m0 + rr) * 1024 + ct * 128 + tx * 4;
        *(float4*)&g_pre[base]      = make_float4(val[0], val[1], val[2], val[3]);
        *(float4*)&g_pre[base + 64] = make_float4(val[4], val[5], val[6], val[7]);
    }
}

// ========================== Kernel C ==========================
// 16 clusters x 8 CTAs x 256 threads. CTA owns 32 H-dims; cluster owns 16 batches.
// smem: [0,32768) swizzled weights; [32768,40960) h double buffer; [40960,43008) red.
#define HOFF 32768
#define ROFF 40960

__global__ __launch_bounds__(256, 1) __cluster_dims__(8, 1, 1)
void kernelC(const float* __restrict__ soil,
             const float* __restrict__ w_ih, const float* __restrict__ w_fo,
             const float* __restrict__ w_oh, const float* __restrict__ w_gh,
             float* __restrict__ out)
{
    extern __shared__ float smC[];
    int tid = threadIdx.x;
    int d = tid & 31, w = tid >> 5;
    int kh = w & 1, bg = w >> 1;
    unsigned rank; asm("mov.u32 %0, %%cluster_ctarank;" : "=r"(rank));
    int cl = blockIdx.x >> 3;
    int dimBase = (int)rank * 32;

    const float* wsrc0[4] = {w_ih, w_fo, w_oh, w_gh};
    for (int c = tid; c < 8192; c += 256) {
        int g = c >> 11, rem = c & 2047, dd = rem >> 6, kq = rem & 63;
        float4 v = *(const float4*)&wsrc0[g][(size_t)(dimBase + dd) * Hn + kq * 4];
        *(float4*)&smC[g * 8192 + dd * 256 + ((kq ^ (dd & 7)) << 2)] = v;
    }
    for (int i = tid; i < 8192; i += 256) smC[HOFF + i] = 0.0f;
    __syncthreads();
    asm volatile("barrier.cluster.arrive.aligned;" ::: "memory");
    asm volatile("barrier.cluster.wait.aligned;" ::: "memory");

    uint32_t smu;
    asm("{ .reg .u64 t0; cvta.to.shared.u64 t0, %1; cvt.u32.u64 %0, t0; }" : "=r"(smu) : "l"(smC));

    float cc[4] = {0,0,0,0}, sc[4] = {0,0,0,0}, sc2[4] = {0,0,0,0}, scs[4] = {0,0,0,0};
    float ss[4] = {0,0,0,0}, ss2[4] = {0,0,0,0};

    int b0 = bg * 4;
    int gb0 = cl * 16 + b0;
    const size_t CO = (size_t)Bn * Sn * Hn;
    const float* Wd0 = &smC[0 * 8192 + d * 256];
    const float* Wd1 = &smC[1 * 8192 + d * 256];
    const float* Wd2 = &smC[2 * 8192 + d * 256];
    const float* Wd3 = &smC[3 * 8192 + d * 256];
    int dsw = d & 7;

    for (int t = 0; t < Sn; t++) {
        int pb = t & 1;
        float pre[4][4], so[4];
        if (kh == 0) {
#pragma unroll
            for (int j = 0; j < 4; j++) {
                size_t mrow = ((size_t)t * 256 + gb0 + j) * 1024 + dimBase + d;
#pragma unroll
                for (int g = 0; g < 4; g++) pre[g][j] = g_pre[mrow + g * 256];
                so[j] = soil[(size_t)(gb0 + j) * Sn + t];
            }
        }
        float acc[4][4];
#pragma unroll
        for (int g = 0; g < 4; g++)
#pragma unroll
            for (int j = 0; j < 4; j++) acc[g][j] = 0.0f;

        const float* hb = &smC[HOFF + pb * 4096];
        int kqs = kh * 32;
#pragma unroll 4
        for (int kq = kqs; kq < kqs + 32; kq++) {
            int o = (kq ^ dsw) << 2;
            float4 w0 = *(const float4*)&Wd0[o];
            float4 w1 = *(const float4*)&Wd1[o];
            float4 w2 = *(const float4*)&Wd2[o];
            float4 w3 = *(const float4*)&Wd3[o];
#pragma unroll
            for (int j = 0; j < 4; j++) {
                float4 hv = *(const float4*)&hb[(b0 + j) * 256 + kq * 4];
                acc[0][j] = fmaf(w0.x, hv.x, acc[0][j]); acc[0][j] = fmaf(w0.y, hv.y, acc[0][j]);
                acc[0][j] = fmaf(w0.z, hv.z, acc[0][j]); acc[0][j] = fmaf(w0.w, hv.w, acc[0][j]);
                acc[1][j] = fmaf(w1.x, hv.x, acc[1][j]); acc[1][j] = fmaf(w1.y, hv.y, acc[1][j]);
                acc[1][j] = fmaf(w1.z, hv.z, acc[1][j]); acc[1][j] = fmaf(w1.w, hv.w, acc[1][j]);
                acc[2][j] = fmaf(w2.x, hv.x, acc[2][j]); acc[2][j] = fmaf(w2.y, hv.y, acc[2][j]);
                acc[2][j] = fmaf(w2.z, hv.z, acc[2][j]); acc[2][j] = fmaf(w2.w, hv.w, acc[2][j]);
                acc[3][j] = fmaf(w3.x, hv.x, acc[3][j]); acc[3][j] = fmaf(w3.y, hv.y, acc[3][j]);
                acc[3][j] = fmaf(w3.z, hv.z, acc[3][j]); acc[3][j] = fmaf(w3.w, hv.w, acc[3][j]);
            }
        }
        if (kh == 1) {
#pragma unroll
            for (int g = 0; g < 4; g++)
#pragma unroll
                for (int j = 0; j < 4; j++)
                    smC[ROFF + (bg * 16 + g * 4 + j) * 32 + d] = acc[g][j];
        }
        __syncthreads();
        if (kh == 0) {
            float n_f = fmaxf((float)t, 1.0f);
            float inv_n = 1.0f / n_f;
#pragma unroll
            for (int j = 0; j < 4; j++) {
                float di = acc[0][j] + smC[ROFF + (bg * 16 + 0 * 4 + j) * 32 + d];
                float df = acc[1][j] + smC[ROFF + (bg * 16 + 1 * 4 + j) * 32 + d];
                float dо = acc[2][j] + smC[ROFF + (bg * 16 + 2 * 4 + j) * 32 + d];
                float dg = acc[3][j] + smC[ROFF + (bg * 16 + 3 * 4 + j) * 32 + d];
                float iv = sigf(pre[0][j] + di);
                float fv = sigf(pre[1][j] + df);
                float ov = sigf(pre[2][j] + dо);
                float gv = tanhf(pre[3][j] + dg);
                float c_raw = fv * cc[j] + iv * gv;
                float hn = ov * tanhf(c_raw);
                float cov   = scs[j] - sc[j] * (ss[j] * inv_n);
                float var_c = sc2[j] - sc[j] * sc[j] * inv_n;
                float var_s = ss2[j] - ss[j] * ss[j] * inv_n;
                float den2 = var_c * var_s;
                float r = 0.0f;
                if (den2 > 0.0f) {
                    float den = sqrtf(den2);
                    if (den > 1e-12f) r = cov / den;
                }
                float cn = c_raw * (fabsf(r) + 1.0f);
                cc[j] = cn;
                sc[j] += cn; sc2[j] = fmaf(cn, cn, sc2[j]); scs[j] = fmaf(cn, so[j], scs[j]);
                ss[j] += so[j]; ss2[j] = fmaf(so[j], so[j], ss2[j]);
                size_t oidx = ((size_t)(gb0 + j) * Sn + t) * Hn + dimBase + d;
                out[oidx] = hn;
                out[CO + oidx] = cn;
                uint32_t la = smu + (uint32_t)((HOFF + ((t + 1) & 1) * 4096 + (b0 + j) * 256 + dimBase + d) * 4);
#pragma unroll
                for (int rr = 0; rr < 8; rr++) {
                    uint32_t ra;
                    asm volatile("mapa.shared::cluster.u32 %0, %1, %2;" : "=r"(ra) : "r"(la), "r"(rr));
                    asm volatile("st.shared::cluster.f32 [%0], %1;" :: "r"(ra), "f"(hn) : "memory");
                }
            }
        }
        __syncthreads();
        asm volatile("barrier.cluster.arrive.aligned;" ::: "memory");
        asm volatile("barrier.cluster.wait.aligned;" ::: "memory");
    }
}

// ========================== launcher ==========================
extern "C" void kernel_launch(void* const* d_in, const int* in_sizes, int n_in,
                              void* d_out, int out_size) {
    const float* x_input = (const float*)d_in[0];
    const float* x_sca   = (const float*)d_in[1];
    const float* soil    = (const float*)d_in[2];
    const float* w_ix = (const float*)d_in[3];
    const float* w_ih = (const float*)d_in[4];
    const float* w_ia = (const float*)d_in[5];
    const float* b_i  = (const float*)d_in[6];
    const float* w_fx = (const float*)d_in[7];
    const float* w_fo = (const float*)d_in[8];
    const float* w_fa = (const float*)d_in[9];
    const float* b_f  = (const float*)d_in[10];
    const float* w_ox = (const float*)d_in[11];
    const float* w_oh = (const float*)d_in[12];
    const float* w_oa = (const float*)d_in[13];
    const float* b_o  = (const float*)d_in[14];
    const float* w_gx = (const float*)d_in[15];
    const float* w_gh = (const float*)d_in[16];
    const float* b_g  = (const float*)d_in[17];
    const float* w_a  = (const float*)d_in[18];
    const float* b_a  = (const float*)d_in[19];
    float* out = (float*)d_out;

    kernelA<<<Mn / 64, 256>>>(x_sca, w_a, b_a);
    dim3 gB(8, Mn / 128);
    kernelB<<<gB, 256>>>(x_input, w_ix, w_ia, b_i, w_fx, w_fa, b_f,
                         w_ox, w_oa, b_o, w_gx, b_g);
    cudaFuncSetAttribute(kernelC, cudaFuncAttributeMaxDynamicSharedMemorySize, 172032);
    kernelC<<<128, 256, 172032>>>(soil, w_ih, w_fo, w_oh, w_gh, out);
}